// round 9
// baseline (speedup 1.0000x reference)
#include <cuda_runtime.h>
#include <cuda_fp16.h>
#include <math.h>
#include <stdint.h>

// Problem constants
#define BB   4
#define LSEQ 4096
#define DD   1024
#define NLBL 8921
#define NLP  8960          // padded label count (multiple of 128/256)
#define NSEG 8
#define SEGL (LSEQ / NSEG) // 512

// GEMM tiling: CTA 128(M) x 128(N) x 64(K halfs), 4 warps, warp tile 64x64
#define Bb   128
#define BN   128
#define BKH  64            // K elements per chunk (halfs), 128 B per row
#define NTHR 128
#define STAGES 3
#define TILE_BYTES (Bb * 128)                 // 16 KB per operand tile
#define STG_BYTES  (2 * TILE_BYTES)           // 32 KB per stage
#define SMEM_BYTES (STAGES * STG_BYTES)       // 96 KB

// ---------------- scratch (device globals; no allocation allowed) ----------
__device__ __half g_l1h[(size_t)BB * LSEQ * DD];       // 32 MB  (l1 in fp16)
__device__ __half g_scoresh[(size_t)BB * LSEQ * NLP];  // 293 MB fp16 scores
__device__ __half g_xh [(size_t)BB * LSEQ * DD];       // 32 MB  fp16 x
__device__ __half g_xth[(size_t)BB * DD * LSEQ];       // 32 MB  fp16 x^T
__device__ __half g_w1h[(size_t)DD * DD];              // 2 MB
__device__ __half g_w2h[(size_t)NLP * DD];             // 18 MB  padded W2
__device__ __half g_attnh[(size_t)BB * NLP * LSEQ];    // 293 MB fp16 attn
__device__ float g_pmax[BB * NSEG * NLP];
__device__ float g_psum[BB * NSEG * NLP];
__device__ float g_max [BB * NLP];
__device__ float g_rsum[BB * NLP];

// ======================= helpers ===========================================
__device__ __forceinline__ uint32_t smem_u32(const void* p) {
    uint32_t a;
    asm("{ .reg .u64 t; cvta.to.shared.u64 t, %1; cvt.u32.u64 %0, t; }"
        : "=r"(a) : "l"(p));
    return a;
}
__device__ __forceinline__ void cp_async16(uint32_t dst, const void* src) {
    asm volatile("cp.async.cg.shared.global [%0], [%1], 16;"
        :: "r"(dst), "l"(src));
}
#define CP_COMMIT() asm volatile("cp.async.commit_group;" ::: "memory")
#define CP_WAIT(n)  asm volatile("cp.async.wait_group %0;" :: "n"(n) : "memory")

__device__ __forceinline__ void mma_f16(float* c, const uint32_t* a, const uint32_t* b) {
    asm volatile(
        "mma.sync.aligned.m16n8k16.row.col.f32.f16.f16.f32 "
        "{%0,%1,%2,%3}, {%4,%5,%6,%7}, {%8,%9}, {%0,%1,%2,%3};"
        : "+f"(c[0]), "+f"(c[1]), "+f"(c[2]), "+f"(c[3])
        : "r"(a[0]), "r"(a[1]), "r"(a[2]), "r"(a[3]),
          "r"(b[0]), "r"(b[1]));
}

// ldmatrix x4 of 8x8 b16 tiles (fp16-native fragment loads)
__device__ __forceinline__ void ldsm4(uint32_t& r0, uint32_t& r1,
                                      uint32_t& r2, uint32_t& r3, uint32_t addr) {
    asm volatile("ldmatrix.sync.aligned.m8n8.x4.shared.b16 {%0,%1,%2,%3}, [%4];"
        : "=r"(r0), "=r"(r1), "=r"(r2), "=r"(r3) : "r"(addr));
}

// byte offset of 16B chunk c16 (0..7) in row r of a (rows x 128B) tile;
// XOR swizzle keeps cp.async 16B chunks intact, conflict-free ldmatrix.
__device__ __forceinline__ uint32_t swoffh(int r, int c16) {
    return ((uint32_t)r << 7) + (uint32_t)(((c16) ^ (r & 7)) << 4);
}

// ---------------------------------------------------------------------------
// fp16 mma.sync GEMM (NT): C[M x Nc] = A[M x K] @ B[* x K]^T, fp32 accum.
// CTA 128x128, 4 warps (2Mx2N), warp tile 64x64, BKH=64 halfs/chunk,
// 3-stage cp.async, 2 CTAs/SM. A rows clamped if CLAMP_A; output rows
// guarded to Mv if GUARD_M. CT = float or __half output.
// ---------------------------------------------------------------------------
template <typename CT, bool DO_TANH, bool GUARD_M, bool CLAMP_A>
__global__ __launch_bounds__(NTHR, 2) void tc_gemm(
    const __half* __restrict__ A, const __half* __restrict__ Bm, CT* __restrict__ C,
    int Mv, int Nc, int K, long sAb, long sBb, long sCb)
{
    extern __shared__ char smc[];
    const uint32_t sbase = smem_u32(smc);
    const int tid  = threadIdx.x;
    const int wid  = tid >> 5;
    const int lid  = tid & 31;
    const int g    = lid >> 2;
    const int tig  = lid & 3;
    const int wrow = wid & 1;    // 0..1 (M, 64 rows each)
    const int wcol = wid >> 1;   // 0..1 (N, 64 cols each)

    A  += (long)blockIdx.z * sAb;
    Bm += (long)blockIdx.z * sBb;
    C  += (long)blockIdx.z * sCb;

    const long row0 = (long)blockIdx.y * Bb;
    const long col0 = (long)blockIdx.x * BN;
    const int  nch  = K / BKH;

    // tile-load mapping: 128 threads, 16 rows/pass, 8 16B-chunks per row
    const int lr = tid >> 3;        // 0..15
    const int lc = tid & 7;         // 16B chunk column

    // ldmatrix lane geometry
    const int m_rin = ((lid >> 3) & 1) * 8 + (lid & 7);
    const int m_k16 = (lid >> 4);   // 0 or 1 (16B = 8 halfs)

    float acc[4][8][4];
    #pragma unroll
    for (int mt = 0; mt < 4; mt++)
        #pragma unroll
        for (int nt = 0; nt < 8; nt++)
            #pragma unroll
            for (int q = 0; q < 4; q++) acc[mt][nt][q] = 0.f;

    auto issue = [&](int i, int s) {
        const __half* Ag = A + (long)i * BKH;
        const __half* Bg = Bm + col0 * K + (long)i * BKH;
        uint32_t st = sbase + s * STG_BYTES;
        #pragma unroll
        for (int t = 0; t < 8; t++) {          // A: 128 rows, 16/pass
            int r = lr + t * 16;
            long rA = row0 + r;
            if (CLAMP_A && rA > Mv - 1) rA = Mv - 1;
            cp_async16(st + swoffh(r, lc), Ag + rA * K + lc * 8);
        }
        uint32_t stB = st + TILE_BYTES;
        #pragma unroll
        for (int t = 0; t < 8; t++) {          // B: 128 rows
            int r = lr + t * 16;
            cp_async16(stB + swoffh(r, lc), Bg + (long)r * K + lc * 8);
        }
    };

    #pragma unroll
    for (int i = 0; i < STAGES - 1; i++) { issue(i, i); CP_COMMIT(); }

    for (int i = 0; i < nch; i++) {
        CP_WAIT(STAGES - 2);
        __syncthreads();

        const int inext = i + STAGES - 1;
        if (inext < nch) issue(inext, inext % STAGES);
        CP_COMMIT();

        const uint32_t sAu = sbase + (i % STAGES) * STG_BYTES;
        const uint32_t sBu = sAu + TILE_BYTES;

        #pragma unroll
        for (int ks = 0; ks < 4; ks++) {       // 4 k-steps of 16 halfs
            const int kb16 = ks * 2;           // 16B-chunk base
            uint32_t af[4][4], bf[8][2];
            #pragma unroll
            for (int mt = 0; mt < 4; mt++) {
                int r = wrow * 64 + mt * 16 + m_rin;
                ldsm4(af[mt][0], af[mt][1], af[mt][2], af[mt][3],
                      sAu + swoffh(r, kb16 + m_k16));
            }
            #pragma unroll
            for (int j = 0; j < 4; j++) {
                int r = wcol * 64 + j * 16 + m_rin;
                ldsm4(bf[2 * j][0], bf[2 * j + 1][0], bf[2 * j][1], bf[2 * j + 1][1],
                      sBu + swoffh(r, kb16 + m_k16));
            }
            #pragma unroll
            for (int mt = 0; mt < 4; mt++)
                #pragma unroll
                for (int nt = 0; nt < 8; nt++)
                    mma_f16(acc[mt][nt], af[mt], bf[nt]);
        }
    }

    // epilogue: rows g and g+8 per m-tile; float2 (CT=float) or half2 stores
    #pragma unroll
    for (int mt = 0; mt < 4; mt++) {
        long r0 = row0 + wrow * 64 + mt * 16 + g;
        long r1 = r0 + 8;
        bool ok0 = !GUARD_M || (r0 < Mv);
        bool ok1 = !GUARD_M || (r1 < Mv);
        #pragma unroll
        for (int nt = 0; nt < 8; nt++) {
            long cc = col0 + wcol * 64 + nt * 8 + 2 * tig;
            float2 v0 = make_float2(acc[mt][nt][0], acc[mt][nt][1]);
            float2 v1 = make_float2(acc[mt][nt][2], acc[mt][nt][3]);
            if (DO_TANH) {
                v0.x = tanhf(v0.x); v0.y = tanhf(v0.y);
                v1.x = tanhf(v1.x); v1.y = tanhf(v1.y);
            }
            if (sizeof(CT) == 4) {
                if (ok0) *reinterpret_cast<float2*>((float*)&C[r0 * Nc + cc]) = v0;
                if (ok1) *reinterpret_cast<float2*>((float*)&C[r1 * Nc + cc]) = v1;
            } else {
                if (ok0) *reinterpret_cast<__half2*>((__half*)&C[r0 * Nc + cc]) =
                    __floats2half2_rn(v0.x, v0.y);
                if (ok1) *reinterpret_cast<__half2*>((__half*)&C[r1 * Nc + cc]) =
                    __floats2half2_rn(v1.x, v1.y);
            }
        }
    }
}

// ---------------------------------------------------------------------------
// conversion helpers
// ---------------------------------------------------------------------------
__global__ void tohalf(const float* __restrict__ src, __half* __restrict__ dst, int n)
{
    int i = blockIdx.x * 256 + threadIdx.x;
    if (i < n) dst[i] = __float2half(src[i]);
}
__global__ void w2pad(const float* __restrict__ W2, __half* __restrict__ dst)
{
    int i = blockIdx.x * 256 + threadIdx.x;
    if (i >= NLP * DD) return;
    int row = i / DD;
    dst[i] = (row < NLBL) ? __float2half(W2[i]) : __float2half(0.f);
}

// ---------------------------------------------------------------------------
// xprep: read x once; write xh = f16(x) (same layout) and xth = f16(x)^T
// ---------------------------------------------------------------------------
__global__ void xprep(const float* __restrict__ x, __half* __restrict__ xh,
                      __half* __restrict__ xT)
{
    __shared__ float tile[32][33];
    int b  = blockIdx.z;
    int d0 = blockIdx.x * 32;
    int l0 = blockIdx.y * 32;
    int tx = threadIdx.x, ty = threadIdx.y;  // 32 x 8
    #pragma unroll
    for (int i = 0; i < 4; i++) {
        size_t idx = ((size_t)b * LSEQ + l0 + ty + i * 8) * DD + d0 + tx;
        float v = x[idx];
        xh[idx] = __float2half(v);
        tile[ty + i * 8][tx] = v;
    }
    __syncthreads();
    #pragma unroll
    for (int i = 0; i < 4; i++)
        xT[((size_t)b * DD + d0 + ty + i * 8) * LSEQ + l0 + tx] =
            __float2half(tile[tx][ty + i * 8]);
}

// ---------------------------------------------------------------------------
// Softmax over L of fp16 scores[B, L, NLP], half2: 2 columns per thread.
// 224 threads -> 448 columns per block; grid.x = NLP/448 = 20.
// Padded columns (>= NLBL) contain zeros - valid math, ignored later.
// ---------------------------------------------------------------------------
__global__ void softmax_part(const __half2* __restrict__ scores2)
{
    int p = blockIdx.x * 224 + threadIdx.x;   // half2 pair index < NLP/2
    int s = blockIdx.y;
    int b = blockIdx.z;
    const int W2P = NLP / 2;
    float m0 = -1e30f, m1 = -1e30f, s0 = 0.f, s1 = 0.f;
    const __half2* q = scores2 + ((size_t)b * LSEQ + (size_t)s * SEGL) * W2P + p;
    #pragma unroll 4
    for (int l = 0; l < SEGL; l++) {
        float2 v = __half22float2(q[(size_t)l * W2P]);
        if (v.x <= m0) { s0 += __expf(v.x - m0); }
        else           { s0 = s0 * __expf(m0 - v.x) + 1.f; m0 = v.x; }
        if (v.y <= m1) { s1 += __expf(v.y - m1); }
        else           { s1 = s1 * __expf(m1 - v.y) + 1.f; m1 = v.y; }
    }
    int n = 2 * p;
    g_pmax[(b * NSEG + s) * NLP + n] = m0;
    g_psum[(b * NSEG + s) * NLP + n] = s0;
    g_pmax[(b * NSEG + s) * NLP + n + 1] = m1;
    g_psum[(b * NSEG + s) * NLP + n + 1] = s1;
}

__global__ void softmax_comb()
{
    int n = blockIdx.x * 256 + threadIdx.x;
    int b = blockIdx.z;
    float m = -1e30f;
    #pragma unroll
    for (int s = 0; s < NSEG; s++)
        m = fmaxf(m, g_pmax[(b * NSEG + s) * NLP + n]);
    float sum = 0.f;
    #pragma unroll
    for (int s = 0; s < NSEG; s++)
        sum += g_psum[(b * NSEG + s) * NLP + n] * __expf(g_pmax[(b * NSEG + s) * NLP + n] - m);
    g_max [b * NLP + n] = m;
    g_rsum[b * NLP + n] = 1.f / sum;
}

// ---------------------------------------------------------------------------
// attn[b,n,l] = exp(scores[b,l,n]-max)*rsum (fp32, exact -> output) and
// attnh = f16(attn) (feeds GEMM3). scores read as fp16.
// ---------------------------------------------------------------------------
__global__ void attn_transpose(const __half* __restrict__ scores,
                               float* __restrict__ attn, __half* __restrict__ attnh)
{
    __shared__ float tile[32][33];
    int b  = blockIdx.z;
    int n0 = blockIdx.x * 32;
    int l0 = blockIdx.y * 32;
    int tx = threadIdx.x, ty = threadIdx.y;  // 32 x 8

    int n = n0 + tx;
    float m = g_max [b * NLP + n];
    float r = g_rsum[b * NLP + n];
    #pragma unroll
    for (int i = 0; i < 4; i++) {
        int l = l0 + ty + i * 8;
        float v = __expf(__half2float(scores[((size_t)b * LSEQ + l) * NLP + n]) - m) * r;
        tile[ty + i * 8][tx] = v;
    }
    __syncthreads();
    #pragma unroll
    for (int i = 0; i < 4; i++) {
        int n2 = n0 + ty + i * 8;
        int l  = l0 + tx;
        if (n2 < NLBL) {
            float v = tile[tx][ty + i * 8];
            attn[((size_t)b * NLBL + n2) * LSEQ + l] = v;
            attnh[((size_t)b * NLP + n2) * LSEQ + l] = __float2half(v);
        }
    }
}

// ---------------------------------------------------------------------------
extern "C" void kernel_launch(void* const* d_in, const int* in_sizes, int n_in,
                              void* d_out, int out_size)
{
    const float* x  = (const float*)d_in[0];   // [B, L, D]
    const float* W1 = (const float*)d_in[1];   // [D, D]
    const float* W2 = (const float*)d_in[2];   // [NL, D]

    float* out  = (float*)d_out;                          // [B, NL, D]
    float* attn = out + (size_t)BB * NLBL * DD;           // [B, NL, L]

    __half *l1h, *xh, *xth, *w1h, *w2h, *attnh, *scoresh;
    cudaGetSymbolAddress((void**)&l1h, g_l1h);
    cudaGetSymbolAddress((void**)&scoresh, g_scoresh);
    cudaGetSymbolAddress((void**)&xh, g_xh);
    cudaGetSymbolAddress((void**)&xth, g_xth);
    cudaGetSymbolAddress((void**)&w1h, g_w1h);
    cudaGetSymbolAddress((void**)&w2h, g_w2h);
    cudaGetSymbolAddress((void**)&attnh, g_attnh);

    cudaFuncSetAttribute(tc_gemm<__half, true,  false, false>,
                         cudaFuncAttributeMaxDynamicSharedMemorySize, SMEM_BYTES);
    cudaFuncSetAttribute(tc_gemm<__half, false, false, false>,
                         cudaFuncAttributeMaxDynamicSharedMemorySize, SMEM_BYTES);
    cudaFuncSetAttribute(tc_gemm<float,  false, true,  true >,
                         cudaFuncAttributeMaxDynamicSharedMemorySize, SMEM_BYTES);

    // 0) convert operands to fp16; xprep also builds x^T
    xprep<<<dim3(DD / 32, LSEQ / 32, BB), dim3(32, 8)>>>(x, xh, xth);
    tohalf<<<(DD * DD + 255) / 256, 256>>>(W1, w1h, DD * DD);
    w2pad<<<(NLP * DD + 255) / 256, 256>>>(W2, w2h);

    // 1) l1h = f16(tanh(xh @ w1h^T)):  M=16384, N=1024, K=1024
    tc_gemm<__half, true, false, false><<<dim3(DD / BN, (BB * LSEQ) / Bb, 1), NTHR, SMEM_BYTES>>>(
        xh, w1h, l1h, BB * LSEQ, DD, DD, 0, 0, 0);

    // 2) scoresh = f16(l1h @ w2h^T):  M=16384, Nc=NLP, K=1024
    tc_gemm<__half, false, false, false><<<dim3(NLP / BN, (BB * LSEQ) / Bb, 1), NTHR, SMEM_BYTES>>>(
        l1h, w2h, scoresh, BB * LSEQ, NLP, DD, 0, 0, 0);

    // 3) column softmax stats over L (fp16 scores, half2)
    softmax_part<<<dim3(NLP / 448, NSEG, BB), 224>>>((const __half2*)scoresh);
    softmax_comb<<<dim3(NLP / 256, 1, BB), 256>>>();

    // 4) attn (exact fp32, output) + attnh (fp16 for GEMM3)
    attn_transpose<<<dim3(NLP / 32, LSEQ / 32, BB), dim3(32, 8)>>>(scoresh, attn, attnh);

    // 5) out[b] = attnh[b] @ xth[b]^T:  M=8921 (rows clamped), N=1024, K=4096
    tc_gemm<float, false, true, true><<<dim3(DD / BN, NLP / Bb, BB), NTHR, SMEM_BYTES>>>(
        attnh, xth, out, NLBL, DD, LSEQ,
        (long)NLP * LSEQ, (long)DD * LSEQ, (long)NLBL * DD);
}

// round 10
// speedup vs baseline: 1.0001x; 1.0001x over previous
#include <cuda_runtime.h>
#include <cuda_fp16.h>
#include <math.h>
#include <stdint.h>

// Problem constants
#define BB   4
#define LSEQ 4096
#define DD   1024
#define NLBL 8921
#define NLP  8960          // padded label count (multiple of 128/256)
#define NSEG 8
#define SEGL (LSEQ / NSEG) // 512

// GEMM tiling: CTA 128(M) x 128(N) x 64(K halfs), 8 warps, warp tile 32x64
#define Bb   128
#define BN   128
#define BKH  64            // K elements per chunk (halfs), 128 B per row
#define NTHR 256
#define STAGES 3
#define TILE_BYTES (Bb * 128)                 // 16 KB per operand tile
#define STG_BYTES  (2 * TILE_BYTES)           // 32 KB per stage
#define SMEM_BYTES (STAGES * STG_BYTES)       // 96 KB

// ---------------- scratch (device globals; no allocation allowed) ----------
__device__ __half g_l1h[(size_t)BB * LSEQ * DD];       // 32 MB  (l1 in fp16)
__device__ __half g_scoresh[(size_t)BB * LSEQ * NLP];  // 293 MB fp16 scores
__device__ __half g_xh [(size_t)BB * LSEQ * DD];       // 32 MB  fp16 x
__device__ __half g_xth[(size_t)BB * DD * LSEQ];       // 32 MB  fp16 x^T
__device__ __half g_w1h[(size_t)DD * DD];              // 2 MB
__device__ __half g_w2h[(size_t)NLP * DD];             // 18 MB  padded W2
__device__ __half g_attnh[(size_t)BB * NLP * LSEQ];    // 293 MB fp16 attn
__device__ float g_pmax[BB * NSEG * NLP];
__device__ float g_psum[BB * NSEG * NLP];
__device__ float g_max [BB * NLP];
__device__ float g_rsum[BB * NLP];

// ======================= helpers ===========================================
__device__ __forceinline__ uint32_t smem_u32(const void* p) {
    uint32_t a;
    asm("{ .reg .u64 t; cvta.to.shared.u64 t, %1; cvt.u32.u64 %0, t; }"
        : "=r"(a) : "l"(p));
    return a;
}
__device__ __forceinline__ void cp_async16(uint32_t dst, const void* src) {
    asm volatile("cp.async.cg.shared.global [%0], [%1], 16;"
        :: "r"(dst), "l"(src));
}
#define CP_COMMIT() asm volatile("cp.async.commit_group;" ::: "memory")
#define CP_WAIT(n)  asm volatile("cp.async.wait_group %0;" :: "n"(n) : "memory")

__device__ __forceinline__ void mma_f16(float* c, const uint32_t* a, const uint32_t* b) {
    asm volatile(
        "mma.sync.aligned.m16n8k16.row.col.f32.f16.f16.f32 "
        "{%0,%1,%2,%3}, {%4,%5,%6,%7}, {%8,%9}, {%0,%1,%2,%3};"
        : "+f"(c[0]), "+f"(c[1]), "+f"(c[2]), "+f"(c[3])
        : "r"(a[0]), "r"(a[1]), "r"(a[2]), "r"(a[3]),
          "r"(b[0]), "r"(b[1]));
}

// ldmatrix x4 of 8x8 b16 tiles (fp16-native fragment loads)
__device__ __forceinline__ void ldsm4(uint32_t& r0, uint32_t& r1,
                                      uint32_t& r2, uint32_t& r3, uint32_t addr) {
    asm volatile("ldmatrix.sync.aligned.m8n8.x4.shared.b16 {%0,%1,%2,%3}, [%4];"
        : "=r"(r0), "=r"(r1), "=r"(r2), "=r"(r3) : "r"(addr));
}

// byte offset of 16B chunk c16 (0..7) in row r of a (rows x 128B) tile;
// XOR swizzle keeps cp.async 16B chunks intact, conflict-free ldmatrix.
__device__ __forceinline__ uint32_t swoffh(int r, int c16) {
    return ((uint32_t)r << 7) + (uint32_t)(((c16) ^ (r & 7)) << 4);
}

// ---------------------------------------------------------------------------
// fp16 mma.sync GEMM (NT): C[M x Nc] = A[M x K] @ B[* x K]^T, fp32 accum.
// CTA 128x128, 8 warps (4Mx2N), warp tile 32x64, BKH=64 halfs/chunk,
// 3-stage cp.async, 2 CTAs/SM (16 warps/SM). A rows clamped if CLAMP_A;
// output rows guarded to Mv if GUARD_M. CT = float or __half output.
// ---------------------------------------------------------------------------
template <typename CT, bool DO_TANH, bool GUARD_M, bool CLAMP_A>
__global__ __launch_bounds__(NTHR, 2) void tc_gemm(
    const __half* __restrict__ A, const __half* __restrict__ Bm, CT* __restrict__ C,
    int Mv, int Nc, int K, long sAb, long sBb, long sCb)
{
    extern __shared__ char smc[];
    const uint32_t sbase = smem_u32(smc);
    const int tid  = threadIdx.x;
    const int wid  = tid >> 5;
    const int lid  = tid & 31;
    const int g    = lid >> 2;
    const int tig  = lid & 3;
    const int wrow = wid >> 1;   // 0..3 (M, 32 rows each)
    const int wcol = wid & 1;    // 0..1 (N, 64 cols each)

    A  += (long)blockIdx.z * sAb;
    Bm += (long)blockIdx.z * sBb;
    C  += (long)blockIdx.z * sCb;

    const long row0 = (long)blockIdx.y * Bb;
    const long col0 = (long)blockIdx.x * BN;
    const int  nch  = K / BKH;

    // tile-load mapping: 256 threads, 32 rows/pass, 8 16B-chunks per row
    const int lr = tid >> 3;        // 0..31
    const int lc = tid & 7;         // 16B chunk column

    // ldmatrix lane geometry
    const int m_rin = ((lid >> 3) & 1) * 8 + (lid & 7);
    const int m_k16 = (lid >> 4);   // 0 or 1 (16B = 8 halfs)

    float acc[2][8][4];
    #pragma unroll
    for (int mt = 0; mt < 2; mt++)
        #pragma unroll
        for (int nt = 0; nt < 8; nt++)
            #pragma unroll
            for (int q = 0; q < 4; q++) acc[mt][nt][q] = 0.f;

    auto issue = [&](int i, int s) {
        const __half* Ag = A + (long)i * BKH;
        const __half* Bg = Bm + col0 * K + (long)i * BKH;
        uint32_t st = sbase + s * STG_BYTES;
        #pragma unroll
        for (int t = 0; t < 4; t++) {          // A: 128 rows, 32/pass
            int r = lr + t * 32;
            long rA = row0 + r;
            if (CLAMP_A && rA > Mv - 1) rA = Mv - 1;
            cp_async16(st + swoffh(r, lc), Ag + rA * K + lc * 8);
        }
        uint32_t stB = st + TILE_BYTES;
        #pragma unroll
        for (int t = 0; t < 4; t++) {          // B: 128 rows
            int r = lr + t * 32;
            cp_async16(stB + swoffh(r, lc), Bg + (long)r * K + lc * 8);
        }
    };

    #pragma unroll
    for (int i = 0; i < STAGES - 1; i++) { issue(i, i); CP_COMMIT(); }

    for (int i = 0; i < nch; i++) {
        CP_WAIT(STAGES - 2);
        __syncthreads();

        const int inext = i + STAGES - 1;
        if (inext < nch) issue(inext, inext % STAGES);
        CP_COMMIT();

        const uint32_t sAu = sbase + (i % STAGES) * STG_BYTES;
        const uint32_t sBu = sAu + TILE_BYTES;

        #pragma unroll
        for (int ks = 0; ks < 4; ks++) {       // 4 k-steps of 16 halfs
            const int kb16 = ks * 2;           // 16B-chunk base
            uint32_t af[2][4], bf[8][2];
            #pragma unroll
            for (int mt = 0; mt < 2; mt++) {
                int r = wrow * 32 + mt * 16 + m_rin;
                ldsm4(af[mt][0], af[mt][1], af[mt][2], af[mt][3],
                      sAu + swoffh(r, kb16 + m_k16));
            }
            #pragma unroll
            for (int j = 0; j < 4; j++) {
                int r = wcol * 64 + j * 16 + m_rin;
                ldsm4(bf[2 * j][0], bf[2 * j + 1][0], bf[2 * j][1], bf[2 * j + 1][1],
                      sBu + swoffh(r, kb16 + m_k16));
            }
            #pragma unroll
            for (int mt = 0; mt < 2; mt++)
                #pragma unroll
                for (int nt = 0; nt < 8; nt++)
                    mma_f16(acc[mt][nt], af[mt], bf[nt]);
        }
    }

    // epilogue: rows g and g+8 per m-tile; float2 (CT=float) or half2 stores
    #pragma unroll
    for (int mt = 0; mt < 2; mt++) {
        long r0 = row0 + wrow * 32 + mt * 16 + g;
        long r1 = r0 + 8;
        bool ok0 = !GUARD_M || (r0 < Mv);
        bool ok1 = !GUARD_M || (r1 < Mv);
        #pragma unroll
        for (int nt = 0; nt < 8; nt++) {
            long cc = col0 + wcol * 64 + nt * 8 + 2 * tig;
            float2 v0 = make_float2(acc[mt][nt][0], acc[mt][nt][1]);
            float2 v1 = make_float2(acc[mt][nt][2], acc[mt][nt][3]);
            if (DO_TANH) {
                v0.x = tanhf(v0.x); v0.y = tanhf(v0.y);
                v1.x = tanhf(v1.x); v1.y = tanhf(v1.y);
            }
            if (sizeof(CT) == 4) {
                if (ok0) *reinterpret_cast<float2*>((float*)&C[r0 * Nc + cc]) = v0;
                if (ok1) *reinterpret_cast<float2*>((float*)&C[r1 * Nc + cc]) = v1;
            } else {
                if (ok0) *reinterpret_cast<__half2*>((__half*)&C[r0 * Nc + cc]) =
                    __floats2half2_rn(v0.x, v0.y);
                if (ok1) *reinterpret_cast<__half2*>((__half*)&C[r1 * Nc + cc]) =
                    __floats2half2_rn(v1.x, v1.y);
            }
        }
    }
}

// ---------------------------------------------------------------------------
// conversion helpers
// ---------------------------------------------------------------------------
__global__ void tohalf(const float* __restrict__ src, __half* __restrict__ dst, int n)
{
    int i = blockIdx.x * 256 + threadIdx.x;
    if (i < n) dst[i] = __float2half(src[i]);
}
__global__ void w2pad(const float* __restrict__ W2, __half* __restrict__ dst)
{
    int i = blockIdx.x * 256 + threadIdx.x;
    if (i >= NLP * DD) return;
    int row = i / DD;
    dst[i] = (row < NLBL) ? __float2half(W2[i]) : __float2half(0.f);
}

// ---------------------------------------------------------------------------
// xprep: read x once; write xh = f16(x) (same layout) and xth = f16(x)^T
// ---------------------------------------------------------------------------
__global__ void xprep(const float* __restrict__ x, __half* __restrict__ xh,
                      __half* __restrict__ xT)
{
    __shared__ float tile[32][33];
    int b  = blockIdx.z;
    int d0 = blockIdx.x * 32;
    int l0 = blockIdx.y * 32;
    int tx = threadIdx.x, ty = threadIdx.y;  // 32 x 8
    #pragma unroll
    for (int i = 0; i < 4; i++) {
        size_t idx = ((size_t)b * LSEQ + l0 + ty + i * 8) * DD + d0 + tx;
        float v = x[idx];
        xh[idx] = __float2half(v);
        tile[ty + i * 8][tx] = v;
    }
    __syncthreads();
    #pragma unroll
    for (int i = 0; i < 4; i++)
        xT[((size_t)b * DD + d0 + ty + i * 8) * LSEQ + l0 + tx] =
            __float2half(tile[tx][ty + i * 8]);
}

// ---------------------------------------------------------------------------
// Softmax over L of fp16 scores[B, L, NLP], half2: 2 columns per thread.
// ---------------------------------------------------------------------------
__global__ void softmax_part(const __half2* __restrict__ scores2)
{
    int p = blockIdx.x * 224 + threadIdx.x;   // half2 pair index < NLP/2
    int s = blockIdx.y;
    int b = blockIdx.z;
    const int W2P = NLP / 2;
    float m0 = -1e30f, m1 = -1e30f, s0 = 0.f, s1 = 0.f;
    const __half2* q = scores2 + ((size_t)b * LSEQ + (size_t)s * SEGL) * W2P + p;
    #pragma unroll 4
    for (int l = 0; l < SEGL; l++) {
        float2 v = __half22float2(q[(size_t)l * W2P]);
        if (v.x <= m0) { s0 += __expf(v.x - m0); }
        else           { s0 = s0 * __expf(m0 - v.x) + 1.f; m0 = v.x; }
        if (v.y <= m1) { s1 += __expf(v.y - m1); }
        else           { s1 = s1 * __expf(m1 - v.y) + 1.f; m1 = v.y; }
    }
    int n = 2 * p;
    g_pmax[(b * NSEG + s) * NLP + n] = m0;
    g_psum[(b * NSEG + s) * NLP + n] = s0;
    g_pmax[(b * NSEG + s) * NLP + n + 1] = m1;
    g_psum[(b * NSEG + s) * NLP + n + 1] = s1;
}

__global__ void softmax_comb()
{
    int n = blockIdx.x * 256 + threadIdx.x;
    int b = blockIdx.z;
    float m = -1e30f;
    #pragma unroll
    for (int s = 0; s < NSEG; s++)
        m = fmaxf(m, g_pmax[(b * NSEG + s) * NLP + n]);
    float sum = 0.f;
    #pragma unroll
    for (int s = 0; s < NSEG; s++)
        sum += g_psum[(b * NSEG + s) * NLP + n] * __expf(g_pmax[(b * NSEG + s) * NLP + n] - m);
    g_max [b * NLP + n] = m;
    g_rsum[b * NLP + n] = 1.f / sum;
}

// ---------------------------------------------------------------------------
// attn[b,n,l] = exp(scores[b,l,n]-max)*rsum (fp32, exact -> output) and
// attnh = f16(attn) (feeds GEMM3). scores read as fp16.
// ---------------------------------------------------------------------------
__global__ void attn_transpose(const __half* __restrict__ scores,
                               float* __restrict__ attn, __half* __restrict__ attnh)
{
    __shared__ float tile[32][33];
    int b  = blockIdx.z;
    int n0 = blockIdx.x * 32;
    int l0 = blockIdx.y * 32;
    int tx = threadIdx.x, ty = threadIdx.y;  // 32 x 8

    int n = n0 + tx;
    float m = g_max [b * NLP + n];
    float r = g_rsum[b * NLP + n];
    #pragma unroll
    for (int i = 0; i < 4; i++) {
        int l = l0 + ty + i * 8;
        float v = __expf(__half2float(scores[((size_t)b * LSEQ + l) * NLP + n]) - m) * r;
        tile[ty + i * 8][tx] = v;
    }
    __syncthreads();
    #pragma unroll
    for (int i = 0; i < 4; i++) {
        int n2 = n0 + ty + i * 8;
        int l  = l0 + tx;
        if (n2 < NLBL) {
            float v = tile[tx][ty + i * 8];
            attn[((size_t)b * NLBL + n2) * LSEQ + l] = v;
            attnh[((size_t)b * NLP + n2) * LSEQ + l] = __float2half(v);
        }
    }
}

// ---------------------------------------------------------------------------
extern "C" void kernel_launch(void* const* d_in, const int* in_sizes, int n_in,
                              void* d_out, int out_size)
{
    const float* x  = (const float*)d_in[0];   // [B, L, D]
    const float* W1 = (const float*)d_in[1];   // [D, D]
    const float* W2 = (const float*)d_in[2];   // [NL, D]

    float* out  = (float*)d_out;                          // [B, NL, D]
    float* attn = out + (size_t)BB * NLBL * DD;           // [B, NL, L]

    __half *l1h, *xh, *xth, *w1h, *w2h, *attnh, *scoresh;
    cudaGetSymbolAddress((void**)&l1h, g_l1h);
    cudaGetSymbolAddress((void**)&scoresh, g_scoresh);
    cudaGetSymbolAddress((void**)&xh, g_xh);
    cudaGetSymbolAddress((void**)&xth, g_xth);
    cudaGetSymbolAddress((void**)&w1h, g_w1h);
    cudaGetSymbolAddress((void**)&w2h, g_w2h);
    cudaGetSymbolAddress((void**)&attnh, g_attnh);

    cudaFuncSetAttribute(tc_gemm<__half, true,  false, false>,
                         cudaFuncAttributeMaxDynamicSharedMemorySize, SMEM_BYTES);
    cudaFuncSetAttribute(tc_gemm<__half, false, false, false>,
                         cudaFuncAttributeMaxDynamicSharedMemorySize, SMEM_BYTES);
    cudaFuncSetAttribute(tc_gemm<float,  false, true,  true >,
                         cudaFuncAttributeMaxDynamicSharedMemorySize, SMEM_BYTES);

    // 0) convert operands to fp16; xprep also builds x^T
    xprep<<<dim3(DD / 32, LSEQ / 32, BB), dim3(32, 8)>>>(x, xh, xth);
    tohalf<<<(DD * DD + 255) / 256, 256>>>(W1, w1h, DD * DD);
    w2pad<<<(NLP * DD + 255) / 256, 256>>>(W2, w2h);

    // 1) l1h = f16(tanh(xh @ w1h^T)):  M=16384, N=1024, K=1024
    tc_gemm<__half, true, false, false><<<dim3(DD / BN, (BB * LSEQ) / Bb, 1), NTHR, SMEM_BYTES>>>(
        xh, w1h, l1h, BB * LSEQ, DD, DD, 0, 0, 0);

    // 2) scoresh = f16(l1h @ w2h^T):  M=16384, Nc=NLP, K=1024
    tc_gemm<__half, false, false, false><<<dim3(NLP / BN, (BB * LSEQ) / Bb, 1), NTHR, SMEM_BYTES>>>(
        l1h, w2h, scoresh, BB * LSEQ, NLP, DD, 0, 0, 0);

    // 3) column softmax stats over L (fp16 scores, half2)
    softmax_part<<<dim3(NLP / 448, NSEG, BB), 224>>>((const __half2*)scoresh);
    softmax_comb<<<dim3(NLP / 256, 1, BB), 256>>>();

    // 4) attn (exact fp32, output) + attnh (fp16 for GEMM3)
    attn_transpose<<<dim3(NLP / 32, LSEQ / 32, BB), dim3(32, 8)>>>(scoresh, attn, attnh);

    // 5) out[b] = attnh[b] @ xth[b]^T:  M=8921 (rows clamped), N=1024, K=4096
    tc_gemm<float, false, true, true><<<dim3(DD / BN, NLP / Bb, BB), NTHR, SMEM_BYTES>>>(
        attnh, xth, out, NLBL, DD, LSEQ,
        (long)NLP * LSEQ, (long)DD * LSEQ, (long)NLBL * DD);
}

// round 11
// speedup vs baseline: 1.1300x; 1.1299x over previous
#include <cuda_runtime.h>
#include <cuda_fp16.h>
#include <math.h>
#include <stdint.h>

// Problem constants
#define BB   4
#define LSEQ 4096
#define DD   1024
#define NLBL 8921
#define NLP  8960          // padded label count (multiple of 128/256)

// GEMM tiling: CTA 128(M) x 128(N) x 64(K halfs), 4 warps, warp tile 64x64
#define Bb   128
#define BN   128
#define BKH  64            // K elements per chunk (halfs), 128 B per row
#define NTHR 128
#define STAGES 3
#define TILE_BYTES (Bb * 128)                 // 16 KB per operand tile
#define STG_BYTES  (2 * TILE_BYTES)           // 32 KB per stage
#define SMEM_BYTES (STAGES * STG_BYTES)       // 96 KB

// ---------------- scratch (device globals; no allocation allowed) ----------
__device__ __half g_l1h[(size_t)BB * LSEQ * DD];       // 32 MB  (l1 in fp16)
__device__ float  g_E[(size_t)BB * LSEQ * NLP];        // 587 MB fp32 exp(scores)
__device__ __half g_xh [(size_t)BB * LSEQ * DD];       // 32 MB  fp16 x
__device__ __half g_xth[(size_t)BB * DD * LSEQ];       // 32 MB  fp16 x^T
__device__ __half g_w1h[(size_t)DD * DD];              // 2 MB
__device__ __half g_w2h[(size_t)NLP * DD];             // 18 MB  padded W2
__device__ __half g_attnh[(size_t)BB * NLP * LSEQ];    // 293 MB fp16 attn
__device__ float g_sum [BB * NLP];                     // column sum of exp
__device__ float g_rsum[BB * NLP];                     // 1 / sum

// ======================= helpers ===========================================
__device__ __forceinline__ uint32_t smem_u32(const void* p) {
    uint32_t a;
    asm("{ .reg .u64 t; cvta.to.shared.u64 t, %1; cvt.u32.u64 %0, t; }"
        : "=r"(a) : "l"(p));
    return a;
}
__device__ __forceinline__ void cp_async16(uint32_t dst, const void* src) {
    asm volatile("cp.async.cg.shared.global [%0], [%1], 16;"
        :: "r"(dst), "l"(src));
}
#define CP_COMMIT() asm volatile("cp.async.commit_group;" ::: "memory")
#define CP_WAIT(n)  asm volatile("cp.async.wait_group %0;" :: "n"(n) : "memory")

__device__ __forceinline__ void mma_f16(float* c, const uint32_t* a, const uint32_t* b) {
    asm volatile(
        "mma.sync.aligned.m16n8k16.row.col.f32.f16.f16.f32 "
        "{%0,%1,%2,%3}, {%4,%5,%6,%7}, {%8,%9}, {%0,%1,%2,%3};"
        : "+f"(c[0]), "+f"(c[1]), "+f"(c[2]), "+f"(c[3])
        : "r"(a[0]), "r"(a[1]), "r"(a[2]), "r"(a[3]),
          "r"(b[0]), "r"(b[1]));
}

// ldmatrix x4 of 8x8 b16 tiles (fp16-native fragment loads)
__device__ __forceinline__ void ldsm4(uint32_t& r0, uint32_t& r1,
                                      uint32_t& r2, uint32_t& r3, uint32_t addr) {
    asm volatile("ldmatrix.sync.aligned.m8n8.x4.shared.b16 {%0,%1,%2,%3}, [%4];"
        : "=r"(r0), "=r"(r1), "=r"(r2), "=r"(r3) : "r"(addr));
}

// byte offset of 16B chunk c16 (0..7) in row r of a (rows x 128B) tile;
// XOR swizzle keeps cp.async 16B chunks intact, conflict-free ldmatrix.
__device__ __forceinline__ uint32_t swoffh(int r, int c16) {
    return ((uint32_t)r << 7) + (uint32_t)(((c16) ^ (r & 7)) << 4);
}

// ---------------------------------------------------------------------------
// fp16 mma.sync GEMM (NT): C[M x Nc] = A[M x K] @ B[* x K]^T, fp32 accum.
// CTA 128x128, 4 warps (2Mx2N), warp tile 64x64, BKH=64 halfs/chunk,
// 3-stage cp.async, 2 CTAs/SM. A rows clamped if CLAMP_A; output rows
// guarded to Mv if GUARD_M. CT = float or __half output.
// DO_EXPSUM: store exp(acc) instead of acc, and atomicAdd per-column sums
// of exp into gsum[b*NLP + n] (b = row block / LSEQ). Requires CT=float.
// ---------------------------------------------------------------------------
template <typename CT, bool DO_TANH, bool GUARD_M, bool CLAMP_A, bool DO_EXPSUM>
__global__ __launch_bounds__(NTHR, 2) void tc_gemm(
    const __half* __restrict__ A, const __half* __restrict__ Bm, CT* __restrict__ C,
    float* __restrict__ gsum,
    int Mv, int Nc, int K, long sAb, long sBb, long sCb)
{
    extern __shared__ char smc[];
    const uint32_t sbase = smem_u32(smc);
    const int tid  = threadIdx.x;
    const int wid  = tid >> 5;
    const int lid  = tid & 31;
    const int g    = lid >> 2;
    const int tig  = lid & 3;
    const int wrow = wid & 1;    // 0..1 (M, 64 rows each)
    const int wcol = wid >> 1;   // 0..1 (N, 64 cols each)

    A  += (long)blockIdx.z * sAb;
    Bm += (long)blockIdx.z * sBb;
    C  += (long)blockIdx.z * sCb;

    const long row0 = (long)blockIdx.y * Bb;
    const long col0 = (long)blockIdx.x * BN;
    const int  nch  = K / BKH;

    // tile-load mapping: 128 threads, 16 rows/pass, 8 16B-chunks per row
    const int lr = tid >> 3;        // 0..15
    const int lc = tid & 7;         // 16B chunk column

    // ldmatrix lane geometry
    const int m_rin = ((lid >> 3) & 1) * 8 + (lid & 7);
    const int m_k16 = (lid >> 4);   // 0 or 1 (16B = 8 halfs)

    float acc[4][8][4];
    #pragma unroll
    for (int mt = 0; mt < 4; mt++)
        #pragma unroll
        for (int nt = 0; nt < 8; nt++)
            #pragma unroll
            for (int q = 0; q < 4; q++) acc[mt][nt][q] = 0.f;

    auto issue = [&](int i, int s) {
        const __half* Ag = A + (long)i * BKH;
        const __half* Bg = Bm + col0 * K + (long)i * BKH;
        uint32_t st = sbase + s * STG_BYTES;
        #pragma unroll
        for (int t = 0; t < 8; t++) {          // A: 128 rows, 16/pass
            int r = lr + t * 16;
            long rA = row0 + r;
            if (CLAMP_A && rA > Mv - 1) rA = Mv - 1;
            cp_async16(st + swoffh(r, lc), Ag + rA * K + lc * 8);
        }
        uint32_t stB = st + TILE_BYTES;
        #pragma unroll
        for (int t = 0; t < 8; t++) {          // B: 128 rows
            int r = lr + t * 16;
            cp_async16(stB + swoffh(r, lc), Bg + (long)r * K + lc * 8);
        }
    };

    #pragma unroll
    for (int i = 0; i < STAGES - 1; i++) { issue(i, i); CP_COMMIT(); }

    for (int i = 0; i < nch; i++) {
        CP_WAIT(STAGES - 2);
        __syncthreads();

        const int inext = i + STAGES - 1;
        if (inext < nch) issue(inext, inext % STAGES);
        CP_COMMIT();

        const uint32_t sAu = sbase + (i % STAGES) * STG_BYTES;
        const uint32_t sBu = sAu + TILE_BYTES;

        #pragma unroll
        for (int ks = 0; ks < 4; ks++) {       // 4 k-steps of 16 halfs
            const int kb16 = ks * 2;           // 16B-chunk base
            uint32_t af[4][4], bf[8][2];
            #pragma unroll
            for (int mt = 0; mt < 4; mt++) {
                int r = wrow * 64 + mt * 16 + m_rin;
                ldsm4(af[mt][0], af[mt][1], af[mt][2], af[mt][3],
                      sAu + swoffh(r, kb16 + m_k16));
            }
            #pragma unroll
            for (int j = 0; j < 4; j++) {
                int r = wcol * 64 + j * 16 + m_rin;
                ldsm4(bf[2 * j][0], bf[2 * j + 1][0], bf[2 * j][1], bf[2 * j + 1][1],
                      sBu + swoffh(r, kb16 + m_k16));
            }
            #pragma unroll
            for (int mt = 0; mt < 4; mt++)
                #pragma unroll
                for (int nt = 0; nt < 8; nt++)
                    mma_f16(acc[mt][nt], af[mt], bf[nt]);
        }
    }

    if (DO_EXPSUM) {
        // store exp(acc); accumulate per-column sums and atomicAdd to gsum
        float sA[8], sB[8];
        #pragma unroll
        for (int nt = 0; nt < 8; nt++) { sA[nt] = 0.f; sB[nt] = 0.f; }
        #pragma unroll
        for (int mt = 0; mt < 4; mt++) {
            long r0 = row0 + wrow * 64 + mt * 16 + g;
            long r1 = r0 + 8;
            #pragma unroll
            for (int nt = 0; nt < 8; nt++) {
                long cc = col0 + wcol * 64 + nt * 8 + 2 * tig;
                float e0 = __expf(acc[mt][nt][0]);
                float e1 = __expf(acc[mt][nt][1]);
                float e2 = __expf(acc[mt][nt][2]);
                float e3 = __expf(acc[mt][nt][3]);
                sA[nt] += e0 + e2;
                sB[nt] += e1 + e3;
                *reinterpret_cast<float2*>((float*)&C[r0 * Nc + cc]) = make_float2(e0, e1);
                *reinterpret_cast<float2*>((float*)&C[r1 * Nc + cc]) = make_float2(e2, e3);
            }
        }
        #pragma unroll
        for (int nt = 0; nt < 8; nt++) {
            #pragma unroll
            for (int m2 = 4; m2 < 32; m2 <<= 1) {
                sA[nt] += __shfl_xor_sync(0xffffffffu, sA[nt], m2);
                sB[nt] += __shfl_xor_sync(0xffffffffu, sB[nt], m2);
            }
        }
        if (g == 0) {
            int b = (int)(row0 / LSEQ);
            #pragma unroll
            for (int nt = 0; nt < 8; nt++) {
                long cc = col0 + wcol * 64 + nt * 8 + 2 * tig;
                atomicAdd(&gsum[b * NLP + cc],     sA[nt]);
                atomicAdd(&gsum[b * NLP + cc + 1], sB[nt]);
            }
        }
    } else {
        // plain epilogue: rows g and g+8 per m-tile
        #pragma unroll
        for (int mt = 0; mt < 4; mt++) {
            long r0 = row0 + wrow * 64 + mt * 16 + g;
            long r1 = r0 + 8;
            bool ok0 = !GUARD_M || (r0 < Mv);
            bool ok1 = !GUARD_M || (r1 < Mv);
            #pragma unroll
            for (int nt = 0; nt < 8; nt++) {
                long cc = col0 + wcol * 64 + nt * 8 + 2 * tig;
                float2 v0 = make_float2(acc[mt][nt][0], acc[mt][nt][1]);
                float2 v1 = make_float2(acc[mt][nt][2], acc[mt][nt][3]);
                if (DO_TANH) {
                    v0.x = tanhf(v0.x); v0.y = tanhf(v0.y);
                    v1.x = tanhf(v1.x); v1.y = tanhf(v1.y);
                }
                if (sizeof(CT) == 4) {
                    if (ok0) *reinterpret_cast<float2*>((float*)&C[r0 * Nc + cc]) = v0;
                    if (ok1) *reinterpret_cast<float2*>((float*)&C[r1 * Nc + cc]) = v1;
                } else {
                    if (ok0) *reinterpret_cast<__half2*>((__half*)&C[r0 * Nc + cc]) =
                        __floats2half2_rn(v0.x, v0.y);
                    if (ok1) *reinterpret_cast<__half2*>((__half*)&C[r1 * Nc + cc]) =
                        __floats2half2_rn(v1.x, v1.y);
                }
            }
        }
    }
}

// ---------------------------------------------------------------------------
// conversion helpers
// ---------------------------------------------------------------------------
__global__ void tohalf(const float* __restrict__ src, __half* __restrict__ dst, int n)
{
    int i = blockIdx.x * 256 + threadIdx.x;
    if (i < n) dst[i] = __float2half(src[i]);
}
__global__ void w2pad(const float* __restrict__ W2, __half* __restrict__ dst)
{
    int i = blockIdx.x * 256 + threadIdx.x;
    if (i >= NLP * DD) return;
    int row = i / DD;
    dst[i] = (row < NLBL) ? __float2half(W2[i]) : __float2half(0.f);
}
__global__ void rinv_k()
{
    int i = blockIdx.x * 256 + threadIdx.x;
    if (i < BB * NLP) g_rsum[i] = 1.f / g_sum[i];
}

// ---------------------------------------------------------------------------
// xprep: read x once; write xh = f16(x) (same layout) and xth = f16(x)^T
// ---------------------------------------------------------------------------
__global__ void xprep(const float* __restrict__ x, __half* __restrict__ xh,
                      __half* __restrict__ xT)
{
    __shared__ float tile[32][33];
    int b  = blockIdx.z;
    int d0 = blockIdx.x * 32;
    int l0 = blockIdx.y * 32;
    int tx = threadIdx.x, ty = threadIdx.y;  // 32 x 8
    #pragma unroll
    for (int i = 0; i < 4; i++) {
        size_t idx = ((size_t)b * LSEQ + l0 + ty + i * 8) * DD + d0 + tx;
        float v = x[idx];
        xh[idx] = __float2half(v);
        tile[ty + i * 8][tx] = v;
    }
    __syncthreads();
    #pragma unroll
    for (int i = 0; i < 4; i++)
        xT[((size_t)b * DD + d0 + ty + i * 8) * LSEQ + l0 + tx] =
            __float2half(tile[tx][ty + i * 8]);
}

// ---------------------------------------------------------------------------
// attn[b,n,l] = E[b,l,n] * rsum[b,n] (fp32, exact -> output) and
// attnh = f16(attn) (feeds GEMM3). E already holds exp(scores).
// ---------------------------------------------------------------------------
__global__ void attn_transpose(const float* __restrict__ E,
                               float* __restrict__ attn, __half* __restrict__ attnh)
{
    __shared__ float tile[32][33];
    int b  = blockIdx.z;
    int n0 = blockIdx.x * 32;
    int l0 = blockIdx.y * 32;
    int tx = threadIdx.x, ty = threadIdx.y;  // 32 x 8

    int n = n0 + tx;
    float r = g_rsum[b * NLP + n];
    #pragma unroll
    for (int i = 0; i < 4; i++) {
        int l = l0 + ty + i * 8;
        tile[ty + i * 8][tx] = E[((size_t)b * LSEQ + l) * NLP + n] * r;
    }
    __syncthreads();
    #pragma unroll
    for (int i = 0; i < 4; i++) {
        int n2 = n0 + ty + i * 8;
        int l  = l0 + tx;
        if (n2 < NLBL) {
            float v = tile[tx][ty + i * 8];
            attn[((size_t)b * NLBL + n2) * LSEQ + l] = v;
            attnh[((size_t)b * NLP + n2) * LSEQ + l] = __float2half(v);
        }
    }
}

// ---------------------------------------------------------------------------
extern "C" void kernel_launch(void* const* d_in, const int* in_sizes, int n_in,
                              void* d_out, int out_size)
{
    const float* x  = (const float*)d_in[0];   // [B, L, D]
    const float* W1 = (const float*)d_in[1];   // [D, D]
    const float* W2 = (const float*)d_in[2];   // [NL, D]

    float* out  = (float*)d_out;                          // [B, NL, D]
    float* attn = out + (size_t)BB * NLBL * DD;           // [B, NL, L]

    __half *l1h, *xh, *xth, *w1h, *w2h, *attnh;
    float *E, *gsum;
    cudaGetSymbolAddress((void**)&l1h, g_l1h);
    cudaGetSymbolAddress((void**)&E, g_E);
    cudaGetSymbolAddress((void**)&xh, g_xh);
    cudaGetSymbolAddress((void**)&xth, g_xth);
    cudaGetSymbolAddress((void**)&w1h, g_w1h);
    cudaGetSymbolAddress((void**)&w2h, g_w2h);
    cudaGetSymbolAddress((void**)&attnh, g_attnh);
    cudaGetSymbolAddress((void**)&gsum, g_sum);

    cudaFuncSetAttribute(tc_gemm<__half, true,  false, false, false>,
                         cudaFuncAttributeMaxDynamicSharedMemorySize, SMEM_BYTES);
    cudaFuncSetAttribute(tc_gemm<float,  false, false, false, true >,
                         cudaFuncAttributeMaxDynamicSharedMemorySize, SMEM_BYTES);
    cudaFuncSetAttribute(tc_gemm<float,  false, true,  true,  false>,
                         cudaFuncAttributeMaxDynamicSharedMemorySize, SMEM_BYTES);

    // 0) convert operands to fp16; xprep also builds x^T; zero gsum
    xprep<<<dim3(DD / 32, LSEQ / 32, BB), dim3(32, 8)>>>(x, xh, xth);
    tohalf<<<(DD * DD + 255) / 256, 256>>>(W1, w1h, DD * DD);
    w2pad<<<(NLP * DD + 255) / 256, 256>>>(W2, w2h);
    cudaMemsetAsync(gsum, 0, (size_t)BB * NLP * sizeof(float));

    // 1) l1h = f16(tanh(xh @ w1h^T)):  M=16384, N=1024, K=1024
    tc_gemm<__half, true, false, false, false>
        <<<dim3(DD / BN, (BB * LSEQ) / Bb, 1), NTHR, SMEM_BYTES>>>(
        xh, w1h, l1h, gsum, BB * LSEQ, DD, DD, 0, 0, 0);

    // 2) E = exp(l1h @ w2h^T), column sums -> gsum:  M=16384, Nc=NLP, K=1024
    tc_gemm<float, false, false, false, true>
        <<<dim3(NLP / BN, (BB * LSEQ) / Bb, 1), NTHR, SMEM_BYTES>>>(
        l1h, w2h, E, gsum, BB * LSEQ, NLP, DD, 0, 0, 0);

    // 3) rsum = 1 / gsum
    rinv_k<<<(BB * NLP + 255) / 256, 256>>>();

    // 4) attn (exact fp32, output) + attnh (fp16 for GEMM3)
    attn_transpose<<<dim3(NLP / 32, LSEQ / 32, BB), dim3(32, 8)>>>(E, attn, attnh);

    // 5) out[b] = attnh[b] @ xth[b]^T:  M=8921 (rows clamped), N=1024, K=4096
    tc_gemm<float, false, true, true, false>
        <<<dim3(DD / BN, NLP / Bb, BB), NTHR, SMEM_BYTES>>>(
        attnh, xth, out, gsum, NLBL, DD, LSEQ,
        (long)NLP * LSEQ, (long)DD * LSEQ, (long)NLBL * DD);
}

// round 12
// speedup vs baseline: 1.1985x; 1.0606x over previous
#include <cuda_runtime.h>
#include <cuda_fp16.h>
#include <math.h>
#include <stdint.h>

// Problem constants
#define BB   4
#define LSEQ 4096
#define DD   1024
#define NLBL 8921
#define NLP  8960          // padded label count (multiple of 128/256)
#define MALL (BB * LSEQ)   // 16384

// GEMM tiling: CTA 128(M) x 128(N) x 64(K halfs), 4 warps, warp tile 64x64
#define Bb   128
#define BN   128
#define BKH  64            // K elements per chunk (halfs), 128 B per row
#define NTHR 128
#define STAGES 3
#define TILE_BYTES (Bb * 128)                 // 16 KB per operand tile
#define STG_BYTES  (2 * TILE_BYTES)           // 32 KB per stage
#define SMEM_BYTES (STAGES * STG_BYTES)       // 96 KB

// ---------------- scratch (device globals; no allocation allowed) ----------
__device__ __half g_l1h[(size_t)MALL * DD];            // 32 MB  (l1 in fp16)
__device__ __half g_Et[(size_t)NLP * MALL];            // 293 MB fp16 exp(scores)^T
__device__ __half g_xh [(size_t)MALL * DD];            // 32 MB  fp16 x
__device__ __half g_xth[(size_t)BB * DD * LSEQ];       // 32 MB  fp16 x^T
__device__ __half g_w1h[(size_t)DD * DD];              // 2 MB
__device__ __half g_w2h[(size_t)NLP * DD];             // 18 MB  padded W2
__device__ float g_sum [BB * NLP];                     // column sum of exp
__device__ float g_rsum[BB * NLP];                     // 1 / sum

// ======================= helpers ===========================================
__device__ __forceinline__ uint32_t smem_u32(const void* p) {
    uint32_t a;
    asm("{ .reg .u64 t; cvta.to.shared.u64 t, %1; cvt.u32.u64 %0, t; }"
        : "=r"(a) : "l"(p));
    return a;
}
__device__ __forceinline__ void cp_async16(uint32_t dst, const void* src) {
    asm volatile("cp.async.cg.shared.global [%0], [%1], 16;"
        :: "r"(dst), "l"(src));
}
#define CP_COMMIT() asm volatile("cp.async.commit_group;" ::: "memory")
#define CP_WAIT(n)  asm volatile("cp.async.wait_group %0;" :: "n"(n) : "memory")

__device__ __forceinline__ void mma_f16(float* c, const uint32_t* a, const uint32_t* b) {
    asm volatile(
        "mma.sync.aligned.m16n8k16.row.col.f32.f16.f16.f32 "
        "{%0,%1,%2,%3}, {%4,%5,%6,%7}, {%8,%9}, {%0,%1,%2,%3};"
        : "+f"(c[0]), "+f"(c[1]), "+f"(c[2]), "+f"(c[3])
        : "r"(a[0]), "r"(a[1]), "r"(a[2]), "r"(a[3]),
          "r"(b[0]), "r"(b[1]));
}

// ldmatrix x4 of 8x8 b16 tiles (fp16-native fragment loads)
__device__ __forceinline__ void ldsm4(uint32_t& r0, uint32_t& r1,
                                      uint32_t& r2, uint32_t& r3, uint32_t addr) {
    asm volatile("ldmatrix.sync.aligned.m8n8.x4.shared.b16 {%0,%1,%2,%3}, [%4];"
        : "=r"(r0), "=r"(r1), "=r"(r2), "=r"(r3) : "r"(addr));
}

// byte offset of 16B chunk c16 (0..7) in row r of a (rows x 128B) tile;
// XOR swizzle keeps cp.async 16B chunks intact, conflict-free ldmatrix.
__device__ __forceinline__ uint32_t swoffh(int r, int c16) {
    return ((uint32_t)r << 7) + (uint32_t)(((c16) ^ (r & 7)) << 4);
}

// ---------------------------------------------------------------------------
// fp16 mma.sync GEMM (NT): C[M x Nc] = A[M x K(lda)] @ B[* x K]^T, fp32 accum.
// CTA 128x128, 4 warps (2Mx2N), warp tile 64x64, BKH=64 halfs/chunk,
// 3-stage cp.async, 2 CTAs/SM. Output rows guarded to Mv if GUARD_M.
// DO_EXPSUM (CT=__half): store exp(acc) and atomicAdd per-ROW sums of exp
//   into gsum[b*NLP + row], b = col0 / LSEQ (columns are (b,l) flattened).
// DO_SCALE: multiply output row r by g_rsum[blockIdx.z*NLP + r].
// ---------------------------------------------------------------------------
template <typename CT, bool DO_TANH, bool GUARD_M, bool DO_EXPSUM, bool DO_SCALE>
__global__ __launch_bounds__(NTHR, 2) void tc_gemm(
    const __half* __restrict__ A, const __half* __restrict__ Bm, CT* __restrict__ C,
    float* __restrict__ gsum,
    int Mv, int Nc, int K, long lda, long sAb, long sBb, long sCb)
{
    extern __shared__ char smc[];
    const uint32_t sbase = smem_u32(smc);
    const int tid  = threadIdx.x;
    const int wid  = tid >> 5;
    const int lid  = tid & 31;
    const int g    = lid >> 2;
    const int tig  = lid & 3;
    const int wrow = wid & 1;    // 0..1 (M, 64 rows each)
    const int wcol = wid >> 1;   // 0..1 (N, 64 cols each)

    A  += (long)blockIdx.z * sAb;
    Bm += (long)blockIdx.z * sBb;
    C  += (long)blockIdx.z * sCb;

    const long row0 = (long)blockIdx.y * Bb;
    const long col0 = (long)blockIdx.x * BN;
    const int  nch  = K / BKH;

    // tile-load mapping: 128 threads, 16 rows/pass, 8 16B-chunks per row
    const int lr = tid >> 3;        // 0..15
    const int lc = tid & 7;         // 16B chunk column

    // ldmatrix lane geometry
    const int m_rin = ((lid >> 3) & 1) * 8 + (lid & 7);
    const int m_k16 = (lid >> 4);   // 0 or 1 (16B = 8 halfs)

    float acc[4][8][4];
    #pragma unroll
    for (int mt = 0; mt < 4; mt++)
        #pragma unroll
        for (int nt = 0; nt < 8; nt++)
            #pragma unroll
            for (int q = 0; q < 4; q++) acc[mt][nt][q] = 0.f;

    auto issue = [&](int i, int s) {
        const __half* Ag = A + (long)i * BKH;
        const __half* Bg = Bm + col0 * K + (long)i * BKH;
        uint32_t st = sbase + s * STG_BYTES;
        #pragma unroll
        for (int t = 0; t < 8; t++) {          // A: 128 rows, 16/pass
            int r = lr + t * 16;
            cp_async16(st + swoffh(r, lc), Ag + (row0 + r) * lda + lc * 8);
        }
        uint32_t stB = st + TILE_BYTES;
        #pragma unroll
        for (int t = 0; t < 8; t++) {          // B: 128 rows
            int r = lr + t * 16;
            cp_async16(stB + swoffh(r, lc), Bg + (long)r * K + lc * 8);
        }
    };

    #pragma unroll
    for (int i = 0; i < STAGES - 1; i++) { issue(i, i); CP_COMMIT(); }

    for (int i = 0; i < nch; i++) {
        CP_WAIT(STAGES - 2);
        __syncthreads();

        const int inext = i + STAGES - 1;
        if (inext < nch) issue(inext, inext % STAGES);
        CP_COMMIT();

        const uint32_t sAu = sbase + (i % STAGES) * STG_BYTES;
        const uint32_t sBu = sAu + TILE_BYTES;

        #pragma unroll
        for (int ks = 0; ks < 4; ks++) {       // 4 k-steps of 16 halfs
            const int kb16 = ks * 2;           // 16B-chunk base
            uint32_t af[4][4], bf[8][2];
            #pragma unroll
            for (int mt = 0; mt < 4; mt++) {
                int r = wrow * 64 + mt * 16 + m_rin;
                ldsm4(af[mt][0], af[mt][1], af[mt][2], af[mt][3],
                      sAu + swoffh(r, kb16 + m_k16));
            }
            #pragma unroll
            for (int j = 0; j < 4; j++) {
                int r = wcol * 64 + j * 16 + m_rin;
                ldsm4(bf[2 * j][0], bf[2 * j + 1][0], bf[2 * j][1], bf[2 * j + 1][1],
                      sBu + swoffh(r, kb16 + m_k16));
            }
            #pragma unroll
            for (int mt = 0; mt < 4; mt++)
                #pragma unroll
                for (int nt = 0; nt < 8; nt++)
                    mma_f16(acc[mt][nt], af[mt], bf[nt]);
        }
    }

    if (DO_EXPSUM) {
        // store exp(acc) as fp16; per-row sums of exp -> atomicAdd gsum
        const int b = (int)(col0 / LSEQ);
        float rs0[4], rs1[4];
        #pragma unroll
        for (int mt = 0; mt < 4; mt++) { rs0[mt] = 0.f; rs1[mt] = 0.f; }
        #pragma unroll
        for (int mt = 0; mt < 4; mt++) {
            long r0 = row0 + wrow * 64 + mt * 16 + g;
            long r1 = r0 + 8;
            #pragma unroll
            for (int nt = 0; nt < 8; nt++) {
                long cc = col0 + wcol * 64 + nt * 8 + 2 * tig;
                float e0 = __expf(acc[mt][nt][0]);
                float e1 = __expf(acc[mt][nt][1]);
                float e2 = __expf(acc[mt][nt][2]);
                float e3 = __expf(acc[mt][nt][3]);
                rs0[mt] += e0 + e1;
                rs1[mt] += e2 + e3;
                *reinterpret_cast<__half2*>((__half*)&C[r0 * Nc + cc]) =
                    __floats2half2_rn(e0, e1);
                *reinterpret_cast<__half2*>((__half*)&C[r1 * Nc + cc]) =
                    __floats2half2_rn(e2, e3);
            }
        }
        #pragma unroll
        for (int mt = 0; mt < 4; mt++) {
            #pragma unroll
            for (int m2 = 1; m2 < 4; m2 <<= 1) {
                rs0[mt] += __shfl_xor_sync(0xffffffffu, rs0[mt], m2);
                rs1[mt] += __shfl_xor_sync(0xffffffffu, rs1[mt], m2);
            }
        }
        if (tig == 0) {
            #pragma unroll
            for (int mt = 0; mt < 4; mt++) {
                long r0 = row0 + wrow * 64 + mt * 16 + g;
                atomicAdd(&gsum[b * NLP + r0],     rs0[mt]);
                atomicAdd(&gsum[b * NLP + r0 + 8], rs1[mt]);
            }
        }
    } else {
        // plain epilogue: rows g and g+8 per m-tile
        #pragma unroll
        for (int mt = 0; mt < 4; mt++) {
            long r0 = row0 + wrow * 64 + mt * 16 + g;
            long r1 = r0 + 8;
            bool ok0 = !GUARD_M || (r0 < Mv);
            bool ok1 = !GUARD_M || (r1 < Mv);
            float s0 = 1.f, s1 = 1.f;
            if (DO_SCALE) {
                s0 = g_rsum[blockIdx.z * NLP + r0];
                s1 = g_rsum[blockIdx.z * NLP + r1];
            }
            #pragma unroll
            for (int nt = 0; nt < 8; nt++) {
                long cc = col0 + wcol * 64 + nt * 8 + 2 * tig;
                float2 v0 = make_float2(acc[mt][nt][0], acc[mt][nt][1]);
                float2 v1 = make_float2(acc[mt][nt][2], acc[mt][nt][3]);
                if (DO_TANH) {
                    v0.x = tanhf(v0.x); v0.y = tanhf(v0.y);
                    v1.x = tanhf(v1.x); v1.y = tanhf(v1.y);
                }
                if (DO_SCALE) {
                    v0.x *= s0; v0.y *= s0;
                    v1.x *= s1; v1.y *= s1;
                }
                if (sizeof(CT) == 4) {
                    if (ok0) *reinterpret_cast<float2*>((float*)&C[r0 * Nc + cc]) = v0;
                    if (ok1) *reinterpret_cast<float2*>((float*)&C[r1 * Nc + cc]) = v1;
                } else {
                    if (ok0) *reinterpret_cast<__half2*>((__half*)&C[r0 * Nc + cc]) =
                        __floats2half2_rn(v0.x, v0.y);
                    if (ok1) *reinterpret_cast<__half2*>((__half*)&C[r1 * Nc + cc]) =
                        __floats2half2_rn(v1.x, v1.y);
                }
            }
        }
    }
}

// ---------------------------------------------------------------------------
// conversion helpers
// ---------------------------------------------------------------------------
__global__ void tohalf(const float* __restrict__ src, __half* __restrict__ dst, int n)
{
    int i = blockIdx.x * 256 + threadIdx.x;
    if (i < n) dst[i] = __float2half(src[i]);
}
__global__ void w2pad(const float* __restrict__ W2, __half* __restrict__ dst)
{
    int i = blockIdx.x * 256 + threadIdx.x;
    if (i >= NLP * DD) return;
    int row = i / DD;
    dst[i] = (row < NLBL) ? __float2half(W2[i]) : __float2half(0.f);
}
__global__ void rinv_k()
{
    int i = blockIdx.x * 256 + threadIdx.x;
    if (i < BB * NLP) g_rsum[i] = 1.f / g_sum[i];
}

// ---------------------------------------------------------------------------
// xprep: read x once; write xh = f16(x) (same layout) and xth = f16(x)^T
// ---------------------------------------------------------------------------
__global__ void xprep(const float* __restrict__ x, __half* __restrict__ xh,
                      __half* __restrict__ xT)
{
    __shared__ float tile[32][33];
    int b  = blockIdx.z;
    int d0 = blockIdx.x * 32;
    int l0 = blockIdx.y * 32;
    int tx = threadIdx.x, ty = threadIdx.y;  // 32 x 8
    #pragma unroll
    for (int i = 0; i < 4; i++) {
        size_t idx = ((size_t)b * LSEQ + l0 + ty + i * 8) * DD + d0 + tx;
        float v = x[idx];
        xh[idx] = __float2half(v);
        tile[ty + i * 8][tx] = v;
    }
    __syncthreads();
    #pragma unroll
    for (int i = 0; i < 4; i++)
        xT[((size_t)b * DD + d0 + ty + i * 8) * LSEQ + l0 + tx] =
            __float2half(tile[tx][ty + i * 8]);
}

// ---------------------------------------------------------------------------
// attn[b,n,l] = Et[n, b*L + l] * rsum[b,n]  (coalesced; 4 elements/thread)
// ---------------------------------------------------------------------------
__global__ void attn_norm(const __half* __restrict__ Et, float* __restrict__ attn)
{
    int n = blockIdx.y;
    if (n >= NLBL) return;
    int b = blockIdx.z;
    int l = (blockIdx.x * 256 + threadIdx.x) * 4;
    float r = g_rsum[b * NLP + n];
    const __half2* src = reinterpret_cast<const __half2*>(
        Et + (size_t)n * MALL + (size_t)b * LSEQ + l);
    __half2 h0 = src[0], h1 = src[1];
    float2 f0 = __half22float2(h0), f1 = __half22float2(h1);
    float4 v = make_float4(f0.x * r, f0.y * r, f1.x * r, f1.y * r);
    *reinterpret_cast<float4*>(&attn[((size_t)b * NLBL + n) * LSEQ + l]) = v;
}

// ---------------------------------------------------------------------------
extern "C" void kernel_launch(void* const* d_in, const int* in_sizes, int n_in,
                              void* d_out, int out_size)
{
    const float* x  = (const float*)d_in[0];   // [B, L, D]
    const float* W1 = (const float*)d_in[1];   // [D, D]
    const float* W2 = (const float*)d_in[2];   // [NL, D]

    float* out  = (float*)d_out;                          // [B, NL, D]
    float* attn = out + (size_t)BB * NLBL * DD;           // [B, NL, L]

    __half *l1h, *xh, *xth, *w1h, *w2h, *Et;
    float *gsum;
    cudaGetSymbolAddress((void**)&l1h, g_l1h);
    cudaGetSymbolAddress((void**)&Et, g_Et);
    cudaGetSymbolAddress((void**)&xh, g_xh);
    cudaGetSymbolAddress((void**)&xth, g_xth);
    cudaGetSymbolAddress((void**)&w1h, g_w1h);
    cudaGetSymbolAddress((void**)&w2h, g_w2h);
    cudaGetSymbolAddress((void**)&gsum, g_sum);

    cudaFuncSetAttribute(tc_gemm<__half, true,  false, false, false>,
                         cudaFuncAttributeMaxDynamicSharedMemorySize, SMEM_BYTES);
    cudaFuncSetAttribute(tc_gemm<__half, false, false, true,  false>,
                         cudaFuncAttributeMaxDynamicSharedMemorySize, SMEM_BYTES);
    cudaFuncSetAttribute(tc_gemm<float,  false, true,  false, true >,
                         cudaFuncAttributeMaxDynamicSharedMemorySize, SMEM_BYTES);

    // 0) convert operands to fp16; xprep also builds x^T; zero gsum
    xprep<<<dim3(DD / 32, LSEQ / 32, BB), dim3(32, 8)>>>(x, xh, xth);
    tohalf<<<(DD * DD + 255) / 256, 256>>>(W1, w1h, DD * DD);
    w2pad<<<(NLP * DD + 255) / 256, 256>>>(W2, w2h);
    cudaMemsetAsync(gsum, 0, (size_t)BB * NLP * sizeof(float));

    // 1) l1h = f16(tanh(xh @ w1h^T)):  M=16384, N=1024, K=1024
    tc_gemm<__half, true, false, false, false>
        <<<dim3(DD / BN, MALL / Bb, 1), NTHR, SMEM_BYTES>>>(
        xh, w1h, l1h, gsum, MALL, DD, DD, DD, 0, 0, 0);

    // 2) Et[n, m] = f16(exp(w2h[n,:] . l1h[m,:])), row sums -> gsum:
    //    M=NLP, N=MALL, K=1024 (scores computed TRANSPOSED)
    tc_gemm<__half, false, false, true, false>
        <<<dim3(MALL / BN, NLP / Bb, 1), NTHR, SMEM_BYTES>>>(
        w2h, l1h, Et, gsum, NLP, MALL, DD, DD, 0, 0, 0);

    // 3) rsum = 1 / gsum
    rinv_k<<<(BB * NLP + 255) / 256, 256>>>();

    // 4) attn[b,n,l] = Et * rsum  (fp32 output, coalesced, no transpose)
    attn_norm<<<dim3(LSEQ / 1024, NLP, BB), 256>>>(Et, attn);

    // 5) out[b,n,:] = rsum[b,n] * (Et[n, b*L:(b+1)*L] @ xth[b]^T):
    //    M=NLP (guard NLBL), N=1024, K=4096, A row stride = MALL
    tc_gemm<float, false, true, false, true>
        <<<dim3(DD / BN, NLP / Bb, BB), NTHR, SMEM_BYTES>>>(
        Et, xth, out, gsum, NLBL, DD, LSEQ, (long)MALL,
        (long)LSEQ, (long)DD * LSEQ, (long)NLBL * DD);
}

// round 14
// speedup vs baseline: 1.2695x; 1.0592x over previous
#include <cuda_runtime.h>
#include <cuda_fp16.h>
#include <math.h>
#include <stdint.h>

// Problem constants
#define BB   4
#define LSEQ 4096
#define DD   1024
#define NLBL 8921
#define NLP  8960          // padded label count (multiple of 128/256)
#define MALL (BB * LSEQ)   // 16384

// GEMM tiling: CTA 128(M) x 128(N) x 64(K halfs), 4 warps, warp tile 64x64
#define Bb   128
#define BN   128
#define BKH  64            // K elements per chunk (halfs), 128 B per row
#define NTHR 128
#define STAGES 3
#define TILE_BYTES (Bb * 128)                 // 16 KB per operand tile
#define STG_BYTES  (2 * TILE_BYTES)           // 32 KB per stage
#define SMEM_BYTES (STAGES * STG_BYTES)       // 96 KB

// ---------------- scratch (device globals; no allocation allowed) ----------
__device__ __half g_l1h[(size_t)MALL * DD];            // 32 MB  (l1 in fp16)
__device__ __half g_Et[(size_t)NLP * MALL];            // 293 MB fp16 exp(scores)^T
__device__ __half g_xh [(size_t)MALL * DD];            // 32 MB  fp16 x
__device__ __half g_xth[(size_t)BB * DD * LSEQ];       // 32 MB  fp16 x^T
__device__ __half g_w1h[(size_t)DD * DD];              // 2 MB
__device__ __half g_w2h[(size_t)NLP * DD];             // 18 MB  padded W2
__device__ float g_sum [BB * NLP];                     // row sum of exp
__device__ float g_rsum[BB * NLP];                     // 1 / sum

// ======================= helpers ===========================================
__device__ __forceinline__ uint32_t smem_u32(const void* p) {
    uint32_t a;
    asm("{ .reg .u64 t; cvta.to.shared.u64 t, %1; cvt.u32.u64 %0, t; }"
        : "=r"(a) : "l"(p));
    return a;
}
__device__ __forceinline__ void cp_async16(uint32_t dst, const void* src) {
    asm volatile("cp.async.cg.shared.global [%0], [%1], 16;"
        :: "r"(dst), "l"(src));
}
#define CP_COMMIT() asm volatile("cp.async.commit_group;" ::: "memory")
#define CP_WAIT(n)  asm volatile("cp.async.wait_group %0;" :: "n"(n) : "memory")

__device__ __forceinline__ void mma_f16(float* c, const uint32_t* a, const uint32_t* b) {
    asm volatile(
        "mma.sync.aligned.m16n8k16.row.col.f32.f16.f16.f32 "
        "{%0,%1,%2,%3}, {%4,%5,%6,%7}, {%8,%9}, {%0,%1,%2,%3};"
        : "+f"(c[0]), "+f"(c[1]), "+f"(c[2]), "+f"(c[3])
        : "r"(a[0]), "r"(a[1]), "r"(a[2]), "r"(a[3]),
          "r"(b[0]), "r"(b[1]));
}

// ldmatrix x4 of 8x8 b16 tiles (fp16-native fragment loads)
__device__ __forceinline__ void ldsm4(uint32_t& r0, uint32_t& r1,
                                      uint32_t& r2, uint32_t& r3, uint32_t addr) {
    asm volatile("ldmatrix.sync.aligned.m8n8.x4.shared.b16 {%0,%1,%2,%3}, [%4];"
        : "=r"(r0), "=r"(r1), "=r"(r2), "=r"(r3) : "r"(addr));
}

// byte offset of 16B chunk c16 (0..7) in row r of a (rows x 128B) tile;
// XOR swizzle keeps cp.async 16B chunks intact, conflict-free ldmatrix.
__device__ __forceinline__ uint32_t swoffh(int r, int c16) {
    return ((uint32_t)r << 7) + (uint32_t)(((c16) ^ (r & 7)) << 4);
}

// ---------------------------------------------------------------------------
// fp16 mma.sync GEMM (NT): C[M x Nc] = A[M x K(lda)] @ B[* x K]^T, fp32 accum.
// CTA 128x128, 4 warps (2Mx2N), warp tile 64x64, BKH=64 halfs/chunk,
// 3-stage cp.async, 2 CTAs/SM. Output rows guarded to Mv if GUARD_M.
// DO_EXPSUM (CT=__half): store exp(acc) and atomicAdd per-ROW sums of exp
//   into gsum[b*NLP + row], b = col0 / LSEQ (columns are (b,l) flattened).
// DO_SCALE: multiply output row r by g_rsum[blockIdx.z*NLP + r].
// DO_ATTN (GEMM3): CTA x writes attn[b,n,l] = smemA(Et) * rsum for chunks
//   with (i>>3)==blockIdx.x (A-tiles are identical across x-blocks; this
//   partitions the 585 MB attn write perfectly across the grid).
// ---------------------------------------------------------------------------
template <typename CT, bool DO_TANH, bool GUARD_M, bool DO_EXPSUM, bool DO_SCALE,
          bool DO_ATTN>
__global__ __launch_bounds__(NTHR, 2) void tc_gemm(
    const __half* __restrict__ A, const __half* __restrict__ Bm, CT* __restrict__ C,
    float* __restrict__ gsum, float* __restrict__ attnOut,
    int Mv, int Nc, int K, long lda, long sAb, long sBb, long sCb)
{
    extern __shared__ char smc[];
    const uint32_t sbase = smem_u32(smc);
    const int tid  = threadIdx.x;
    const int wid  = tid >> 5;
    const int lid  = tid & 31;
    const int g    = lid >> 2;
    const int tig  = lid & 3;
    const int wrow = wid & 1;    // 0..1 (M, 64 rows each)
    const int wcol = wid >> 1;   // 0..1 (N, 64 cols each)

    A  += (long)blockIdx.z * sAb;
    Bm += (long)blockIdx.z * sBb;
    C  += (long)blockIdx.z * sCb;

    const long row0 = (long)blockIdx.y * Bb;
    const long col0 = (long)blockIdx.x * BN;
    const int  nch  = K / BKH;

    // tile-load mapping: 128 threads, 16 rows/pass, 8 16B-chunks per row
    const int lr = tid >> 3;        // 0..15
    const int lc = tid & 7;         // 16B chunk column

    // ldmatrix lane geometry
    const int m_rin = ((lid >> 3) & 1) * 8 + (lid & 7);
    const int m_k16 = (lid >> 4);   // 0 or 1 (16B = 8 halfs)

    // attn-fusion: rsum per handled row (rows lr + 16p), loaded once
    float rsv[8];
    if (DO_ATTN) {
        #pragma unroll
        for (int p = 0; p < 8; p++) {
            long n = row0 + lr + p * 16;
            rsv[p] = g_rsum[blockIdx.z * NLP + n];
        }
    }

    float acc[4][8][4];
    #pragma unroll
    for (int mt = 0; mt < 4; mt++)
        #pragma unroll
        for (int nt = 0; nt < 8; nt++)
            #pragma unroll
            for (int q = 0; q < 4; q++) acc[mt][nt][q] = 0.f;

    auto issue = [&](int i, int s) {
        const __half* Ag = A + (long)i * BKH;
        const __half* Bg = Bm + col0 * K + (long)i * BKH;
        uint32_t st = sbase + s * STG_BYTES;
        #pragma unroll
        for (int t = 0; t < 8; t++) {          // A: 128 rows, 16/pass
            int r = lr + t * 16;
            cp_async16(st + swoffh(r, lc), Ag + (row0 + r) * lda + lc * 8);
        }
        uint32_t stB = st + TILE_BYTES;
        #pragma unroll
        for (int t = 0; t < 8; t++) {          // B: 128 rows
            int r = lr + t * 16;
            cp_async16(stB + swoffh(r, lc), Bg + (long)r * K + lc * 8);
        }
    };

    #pragma unroll
    for (int i = 0; i < STAGES - 1; i++) { issue(i, i); CP_COMMIT(); }

    for (int i = 0; i < nch; i++) {
        CP_WAIT(STAGES - 2);
        __syncthreads();

        const int inext = i + STAGES - 1;
        if (inext < nch) issue(inext, inext % STAGES);
        CP_COMMIT();

        const uint32_t sAu = sbase + (i % STAGES) * STG_BYTES;
        const uint32_t sBu = sAu + TILE_BYTES;

        #pragma unroll
        for (int ks = 0; ks < 4; ks++) {       // 4 k-steps of 16 halfs
            const int kb16 = ks * 2;           // 16B-chunk base
            uint32_t af[4][4], bf[8][2];
            #pragma unroll
            for (int mt = 0; mt < 4; mt++) {
                int r = wrow * 64 + mt * 16 + m_rin;
                ldsm4(af[mt][0], af[mt][1], af[mt][2], af[mt][3],
                      sAu + swoffh(r, kb16 + m_k16));
            }
            #pragma unroll
            for (int j = 0; j < 4; j++) {
                int r = wcol * 64 + j * 16 + m_rin;
                ldsm4(bf[2 * j][0], bf[2 * j + 1][0], bf[2 * j][1], bf[2 * j + 1][1],
                      sBu + swoffh(r, kb16 + m_k16));
            }
            #pragma unroll
            for (int mt = 0; mt < 4; mt++)
                #pragma unroll
                for (int nt = 0; nt < 8; nt++)
                    mma_f16(acc[mt][nt], af[mt], bf[nt]);
        }

        // attn fusion: this CTA owns chunks [8x .. 8x+7] of the l-range.
        // A-tile (Et rows x 64 l's) is still valid in smem until next sync.
        if (DO_ATTN && (i >> 3) == (int)blockIdx.x) {
            const int l0 = i * BKH;   // l offset within batch
            #pragma unroll
            for (int p = 0; p < 8; p++) {
                int r = lr + p * 16;
                long n = row0 + r;
                if (n < NLBL) {
                    uint32_t h[4];
                    asm volatile("ld.shared.v4.b32 {%0,%1,%2,%3}, [%4];"
                        : "=r"(h[0]), "=r"(h[1]), "=r"(h[2]), "=r"(h[3])
                        : "r"(sAu + swoffh(r, lc)));
                    float rr = rsv[p];
                    float4 v0, v1;
                    {
                        float2 a0 = __half22float2(*reinterpret_cast<__half2*>(&h[0]));
                        float2 a1 = __half22float2(*reinterpret_cast<__half2*>(&h[1]));
                        float2 a2 = __half22float2(*reinterpret_cast<__half2*>(&h[2]));
                        float2 a3 = __half22float2(*reinterpret_cast<__half2*>(&h[3]));
                        v0 = make_float4(a0.x * rr, a0.y * rr, a1.x * rr, a1.y * rr);
                        v1 = make_float4(a2.x * rr, a2.y * rr, a3.x * rr, a3.y * rr);
                    }
                    float* dst = attnOut +
                        ((size_t)blockIdx.z * NLBL + n) * LSEQ + l0 + lc * 8;
                    *reinterpret_cast<float4*>(dst)     = v0;
                    *reinterpret_cast<float4*>(dst + 4) = v1;
                }
            }
        }
    }

    if (DO_EXPSUM) {
        // store exp(acc) as fp16; per-row sums of exp -> atomicAdd gsum
        const int b = (int)(col0 / LSEQ);
        float rs0[4], rs1[4];
        #pragma unroll
        for (int mt = 0; mt < 4; mt++) { rs0[mt] = 0.f; rs1[mt] = 0.f; }
        #pragma unroll
        for (int mt = 0; mt < 4; mt++) {
            long r0 = row0 + wrow * 64 + mt * 16 + g;
            long r1 = r0 + 8;
            #pragma unroll
            for (int nt = 0; nt < 8; nt++) {
                long cc = col0 + wcol * 64 + nt * 8 + 2 * tig;
                float e0 = __expf(acc[mt][nt][0]);
                float e1 = __expf(acc[mt][nt][1]);
                float e2 = __expf(acc[mt][nt][2]);
                float e3 = __expf(acc[mt][nt][3]);
                rs0[mt] += e0 + e1;
                rs1[mt] += e2 + e3;
                *reinterpret_cast<__half2*>((__half*)&C[r0 * Nc + cc]) =
                    __floats2half2_rn(e0, e1);
                *reinterpret_cast<__half2*>((__half*)&C[r1 * Nc + cc]) =
                    __floats2half2_rn(e2, e3);
            }
        }
        #pragma unroll
        for (int mt = 0; mt < 4; mt++) {
            #pragma unroll
            for (int m2 = 1; m2 < 4; m2 <<= 1) {
                rs0[mt] += __shfl_xor_sync(0xffffffffu, rs0[mt], m2);
                rs1[mt] += __shfl_xor_sync(0xffffffffu, rs1[mt], m2);
            }
        }
        if (tig == 0) {
            #pragma unroll
            for (int mt = 0; mt < 4; mt++) {
                long r0 = row0 + wrow * 64 + mt * 16 + g;
                atomicAdd(&gsum[b * NLP + r0],     rs0[mt]);
                atomicAdd(&gsum[b * NLP + r0 + 8], rs1[mt]);
            }
        }
    } else {
        // plain epilogue: rows g and g+8 per m-tile
        #pragma unroll
        for (int mt = 0; mt < 4; mt++) {
            long r0 = row0 + wrow * 64 + mt * 16 + g;
            long r1 = r0 + 8;
            bool ok0 = !GUARD_M || (r0 < Mv);
            bool ok1 = !GUARD_M || (r1 < Mv);
            float s0 = 1.f, s1 = 1.f;
            if (DO_SCALE) {
                s0 = g_rsum[blockIdx.z * NLP + r0];
                s1 = g_rsum[blockIdx.z * NLP + r1];
            }
            #pragma unroll
            for (int nt = 0; nt < 8; nt++) {
                long cc = col0 + wcol * 64 + nt * 8 + 2 * tig;
                float2 v0 = make_float2(acc[mt][nt][0], acc[mt][nt][1]);
                float2 v1 = make_float2(acc[mt][nt][2], acc[mt][nt][3]);
                if (DO_TANH) {
                    v0.x = tanhf(v0.x); v0.y = tanhf(v0.y);
                    v1.x = tanhf(v1.x); v1.y = tanhf(v1.y);
                }
                if (DO_SCALE) {
                    v0.x *= s0; v0.y *= s0;
                    v1.x *= s1; v1.y *= s1;
                }
                if (sizeof(CT) == 4) {
                    if (ok0) *reinterpret_cast<float2*>((float*)&C[r0 * Nc + cc]) = v0;
                    if (ok1) *reinterpret_cast<float2*>((float*)&C[r1 * Nc + cc]) = v1;
                } else {
                    if (ok0) *reinterpret_cast<__half2*>((__half*)&C[r0 * Nc + cc]) =
                        __floats2half2_rn(v0.x, v0.y);
                    if (ok1) *reinterpret_cast<__half2*>((__half*)&C[r1 * Nc + cc]) =
                        __floats2half2_rn(v1.x, v1.y);
                }
            }
        }
    }
}

// ---------------------------------------------------------------------------
// conversion helpers
// ---------------------------------------------------------------------------
__global__ void tohalf(const float* __restrict__ src, __half* __restrict__ dst, int n)
{
    int i = blockIdx.x * 256 + threadIdx.x;
    if (i < n) dst[i] = __float2half(src[i]);
}
__global__ void w2pad(const float* __restrict__ W2, __half* __restrict__ dst)
{
    int i = blockIdx.x * 256 + threadIdx.x;
    if (i >= NLP * DD) return;
    int row = i / DD;
    dst[i] = (row < NLBL) ? __float2half(W2[i]) : __float2half(0.f);
}
__global__ void rinv_k()
{
    int i = blockIdx.x * 256 + threadIdx.x;
    if (i < BB * NLP) g_rsum[i] = 1.f / g_sum[i];
}

// ---------------------------------------------------------------------------
// xprep: read x once; write xh = f16(x) (same layout) and xth = f16(x)^T
// ---------------------------------------------------------------------------
__global__ void xprep(const float* __restrict__ x, __half* __restrict__ xh,
                      __half* __restrict__ xT)
{
    __shared__ float tile[32][33];
    int b  = blockIdx.z;
    int d0 = blockIdx.x * 32;
    int l0 = blockIdx.y * 32;
    int tx = threadIdx.x, ty = threadIdx.y;  // 32 x 8
    #pragma unroll
    for (int i = 0; i < 4; i++) {
        size_t idx = ((size_t)b * LSEQ + l0 + ty + i * 8) * DD + d0 + tx;
        float v = x[idx];
        xh[idx] = __float2half(v);
        tile[ty + i * 8][tx] = v;
    }
    __syncthreads();
    #pragma unroll
    for (int i = 0; i < 4; i++)
        xT[((size_t)b * DD + d0 + ty + i * 8) * LSEQ + l0 + tx] =
            __float2half(tile[tx][ty + i * 8]);
}

// ---------------------------------------------------------------------------
extern "C" void kernel_launch(void* const* d_in, const int* in_sizes, int n_in,
                              void* d_out, int out_size)
{
    const float* x  = (const float*)d_in[0];   // [B, L, D]
    const float* W1 = (const float*)d_in[1];   // [D, D]
    const float* W2 = (const float*)d_in[2];   // [NL, D]

    float* out  = (float*)d_out;                          // [B, NL, D]
    float* attn = out + (size_t)BB * NLBL * DD;           // [B, NL, L]

    __half *l1h, *xh, *xth, *w1h, *w2h, *Et;
    float *gsum;
    cudaGetSymbolAddress((void**)&l1h, g_l1h);
    cudaGetSymbolAddress((void**)&Et, g_Et);
    cudaGetSymbolAddress((void**)&xh, g_xh);
    cudaGetSymbolAddress((void**)&xth, g_xth);
    cudaGetSymbolAddress((void**)&w1h, g_w1h);
    cudaGetSymbolAddress((void**)&w2h, g_w2h);
    cudaGetSymbolAddress((void**)&gsum, g_sum);

    cudaFuncSetAttribute(tc_gemm<__half, true,  false, false, false, false>,
                         cudaFuncAttributeMaxDynamicSharedMemorySize, SMEM_BYTES);
    cudaFuncSetAttribute(tc_gemm<__half, false, false, true,  false, false>,
                         cudaFuncAttributeMaxDynamicSharedMemorySize, SMEM_BYTES);
    cudaFuncSetAttribute(tc_gemm<float,  false, true,  false, true,  true >,
                         cudaFuncAttributeMaxDynamicSharedMemorySize, SMEM_BYTES);

    // 0) convert operands to fp16; xprep also builds x^T; zero gsum
    xprep<<<dim3(DD / 32, LSEQ / 32, BB), dim3(32, 8)>>>(x, xh, xth);
    tohalf<<<(DD * DD + 255) / 256, 256>>>(W1, w1h, DD * DD);
    w2pad<<<(NLP * DD + 255) / 256, 256>>>(W2, w2h);
    cudaMemsetAsync(gsum, 0, (size_t)BB * NLP * sizeof(float));

    // 1) l1h = f16(tanh(xh @ w1h^T)):  M=16384, N=1024, K=1024
    tc_gemm<__half, true, false, false, false, false>
        <<<dim3(DD / BN, MALL / Bb, 1), NTHR, SMEM_BYTES>>>(
        xh, w1h, l1h, gsum, nullptr, MALL, DD, DD, DD, 0, 0, 0);

    // 2) Et[n, m] = f16(exp(w2h[n,:] . l1h[m,:])), row sums -> gsum:
    //    M=NLP, N=MALL, K=1024 (scores computed TRANSPOSED)
    tc_gemm<__half, false, false, true, false, false>
        <<<dim3(MALL / BN, NLP / Bb, 1), NTHR, SMEM_BYTES>>>(
        w2h, l1h, Et, gsum, nullptr, NLP, MALL, DD, DD, 0, 0, 0);

    // 3) rsum = 1 / gsum
    rinv_k<<<(BB * NLP + 255) / 256, 256>>>();

    // 4) out[b,n,:] = rsum[b,n] * (Et[n, b*L:(b+1)*L] @ xth[b]^T), and
    //    attn[b,n,l] = Et * rsum written from smem A-tiles (fused):
    //    M=NLP (guard NLBL), N=1024, K=4096, A row stride = MALL
    tc_gemm<float, false, true, false, true, true>
        <<<dim3(DD / BN, NLP / Bb, BB), NTHR, SMEM_BYTES>>>(
        Et, xth, out, gsum, attn, NLBL, DD, LSEQ, (long)MALL,
        (long)LSEQ, (long)DD * LSEQ, (long)NLBL * DD);
}